// round 2
// baseline (speedup 1.0000x reference)
#include <cuda_runtime.h>
#include <cstdint>

#define D 128
#define BM 128
#define SA_STRIDE 129   // k-major x tile stride; S%8==1 minimizes transpose-store conflicts

// Per-column precomputed constants (c = 1, cs = 1)
__device__ float g_A[D];  // cosh(2*r[d]) / z_norm[d]
__device__ float g_B[D];  // sinh(2*r[d])
__device__ float g_C[D];  // 2 * z_norm[d]

// packed f32x2 FMA (Blackwell FFMA2 — only reachable via PTX)
#define FMA2(d_, a_, b_, c_) \
    asm("fma.rn.f32x2 %0, %1, %2, %3;" : "=l"(d_) : "l"(a_), "l"(b_), "l"(c_))
#define PACK2(d_, lo_, hi_) \
    asm("mov.b64 %0, {%1, %2};" : "=l"(d_) : "r"(lo_), "r"(hi_))
#define UNPACK2(lo_, hi_, s_) \
    asm("mov.b64 {%0, %1}, %2;" : "=r"(lo_), "=r"(hi_) : "l"(s_))

__device__ __forceinline__ float asinh_fast(float v) {
    float av = fabsf(v);
    float s  = sqrtf(fmaf(av, av, 1.0f));
    float l  = __logf(av + s);
    return copysignf(l, v);
}

// ---------------------------------------------------------------------------
// Prelude: per-output-column constants. 1 block x 128 threads, negligible cost.
// ---------------------------------------------------------------------------
__global__ void hmlr_prelude(const float* __restrict__ z, const float* __restrict__ r) {
    int d = threadIdx.x;
    float s = 0.0f;
    #pragma unroll 8
    for (int k = 0; k < D; k++) {
        float v = z[k * D + d];
        s = fmaf(v, v, s);
    }
    float zn = fmaxf(sqrtf(s), 1e-15f);
    float t  = 2.0f * r[d];
    g_A[d] = coshf(t) / zn;
    g_B[d] = sinhf(t);
    g_C[d] = 2.0f * zn;
}

// ---------------------------------------------------------------------------
// Fused GEMM + Poincare MLR epilogue.
// Block: 256 threads, 128 rows x 128 cols tile. Full K resident in SMEM.
// Each thread: 8 rows x 8 cols split (ty*4 / ty*4+64) x (tx*4 / tx*4+64),
// accumulated as 32 packed f32x2 registers.
// ---------------------------------------------------------------------------
__global__ __launch_bounds__(256, 1)
void hmlr_gemm(const float* __restrict__ x, const float* __restrict__ z,
               float* __restrict__ out) {
    extern __shared__ float sm[];
    float* As    = sm;                       // [128 k][129] (x transposed, padded)
    float* Zs    = sm + D * SA_STRIDE;       // [128 k][128 d]
    float* lam_s = Zs + D * D;               // [128] per-row lambda

    const int tid = threadIdx.x;
    const int tx  = tid & 15;
    const int ty  = tid >> 4;
    const int r0  = ty * 4;
    const int c0  = tx * 4;

    const float* xb = x + (size_t)blockIdx.x * BM * D;

    // ---- load z tile (coalesced float4, identity layout) ----
    {
        const float4* z4  = (const float4*)z;
        float4*       Zs4 = (float4*)Zs;
        #pragma unroll
        for (int i = 0; i < 16; i++) Zs4[tid + i * 256] = z4[tid + i * 256];
    }

    // ---- load x tile, transposed to k-major ----
    {
        const float4* x4 = (const float4*)xb;
        #pragma unroll
        for (int it = 0; it < 16; it++) {
            int   idx = tid + it * 256;     // float4 index within tile
            int   row = idx >> 5;
            int   k4  = (idx & 31) << 2;
            float4 v  = x4[idx];
            As[(k4 + 0) * SA_STRIDE + row] = v.x;
            As[(k4 + 1) * SA_STRIDE + row] = v.y;
            As[(k4 + 2) * SA_STRIDE + row] = v.z;
            As[(k4 + 3) * SA_STRIDE + row] = v.w;
        }
    }
    __syncthreads();

    // ---- per-row lambda = 2 / (1 - ||x||^2) ----
    if (tid < BM) {
        float s = 0.0f;
        #pragma unroll 8
        for (int k = 0; k < D; k++) {
            float v = As[k * SA_STRIDE + tid];
            s = fmaf(v, v, s);
        }
        lam_s[tid] = 2.0f / (1.0f - s);
    }
    __syncthreads();

    // ---- main GEMM loop: packed f32x2 accumulators ----
    unsigned long long acc[8][4];
    #pragma unroll
    for (int i = 0; i < 8; i++)
        #pragma unroll
        for (int j = 0; j < 4; j++) acc[i][j] = 0ull;

    #pragma unroll 8
    for (int k = 0; k < D; k++) {
        const float* Ak = &As[k * SA_STRIDE];
        const float* Zk = &Zs[k * D];
        // 4 packed b pairs: cols (c0,c0+1),(c0+2,c0+3),(64+c0,+1),(64+c0+2,+3)
        ulonglong2 B0 = *(const ulonglong2*)(Zk + c0);
        ulonglong2 B1 = *(const ulonglong2*)(Zk + 64 + c0);
        unsigned long long bp[4] = {B0.x, B0.y, B1.x, B1.y};

        float a[8];
        #pragma unroll
        for (int i = 0; i < 4; i++) {
            a[i]     = Ak[r0 + i];
            a[4 + i] = Ak[64 + r0 + i];
        }
        #pragma unroll
        for (int i = 0; i < 8; i++) {
            unsigned long long a2;
            unsigned int au = __float_as_uint(a[i]);
            PACK2(a2, au, au);
            #pragma unroll
            for (int j = 0; j < 4; j++) {
                FMA2(acc[i][j], a2, bp[j], acc[i][j]);
            }
        }
    }

    // ---- epilogue ----
    float lam[8];
    #pragma unroll
    for (int i = 0; i < 4; i++) {
        lam[i]     = lam_s[r0 + i];
        lam[4 + i] = lam_s[64 + r0 + i];
    }
    float cA[8], cB[8], cC[8];
    #pragma unroll
    for (int j = 0; j < 4; j++) {
        int d0 = c0 + j;
        int d1 = 64 + c0 + j;
        cA[j] = g_A[d0];     cB[j] = g_B[d0];     cC[j] = g_C[d0];
        cA[4 + j] = g_A[d1]; cB[4 + j] = g_B[d1]; cC[4 + j] = g_C[d1];
    }

    const size_t rowBase = (size_t)blockIdx.x * BM;
    #pragma unroll
    for (int i = 0; i < 8; i++) {
        int lrow = (i < 4) ? (r0 + i) : (64 + r0 + (i - 4));
        float L   = lam[i];
        float Lm1 = L - 1.0f;
        float v[8];
        #pragma unroll
        for (int jq = 0; jq < 4; jq++) {
            unsigned int u0, u1;
            UNPACK2(u0, u1, acc[i][jq]);
            v[jq * 2 + 0] = __uint_as_float(u0);
            v[jq * 2 + 1] = __uint_as_float(u1);
        }
        float o[8];
        #pragma unroll
        for (int j = 0; j < 8; j++) {
            float inner = v[j];
            float arg   = fmaf(L * inner, cA[j], -Lm1 * cB[j]);
            o[j] = cC[j] * asinh_fast(arg);
        }
        float* orow = out + (rowBase + lrow) * D;
        *(float4*)(orow + c0)      = make_float4(o[0], o[1], o[2], o[3]);
        *(float4*)(orow + 64 + c0) = make_float4(o[4], o[5], o[6], o[7]);
    }
}

// ---------------------------------------------------------------------------
extern "C" void kernel_launch(void* const* d_in, const int* in_sizes, int n_in,
                              void* d_out, int out_size) {
    const float* x = (const float*)d_in[0];   // [N, 128]
    const float* z = (const float*)d_in[1];   // [128, 128]
    const float* r = (const float*)d_in[2];   // [128]
    float* out = (float*)d_out;

    int nRows   = in_sizes[0] / D;            // 131072
    int nBlocks = nRows / BM;                 // 1024

    size_t smemBytes = (size_t)(D * SA_STRIDE + D * D + BM) * sizeof(float);
    cudaFuncSetAttribute(hmlr_gemm, cudaFuncAttributeMaxDynamicSharedMemorySize,
                         (int)smemBytes);

    hmlr_prelude<<<1, D>>>(z, r);
    hmlr_gemm<<<nBlocks, 256, smemBytes>>>(x, z, out);
}

// round 5
// speedup vs baseline: 1.6953x; 1.6953x over previous
#include <cuda_runtime.h>
#include <cuda_bf16.h>
#include <cstdint>

#define D      128
#define BM     64          // rows per tile
#define NTHR   512         // 16 warps
#define RSTRIDE 272        // padded smem row stride (17 x 16B chunks) -> conflict-free ldmatrix

// ---------------- device globals (no allocs allowed) ----------------
__device__ float g_A[D];   // cosh(2r)/||z_col||
__device__ float g_B[D];   // sinh(2r)
__device__ float g_C[D];   // 2*||z_col||
// z^T (n-major, k contiguous) bf16 hi/lo, compact [128][128]
__device__ __align__(16) unsigned char g_zh[D * D * 2];
__device__ __align__(16) unsigned char g_zl[D * D * 2];

// ---------------- smem layout (bytes) ----------------
#define OFF_LAM  0                       // 64 floats
#define OFF_RAW0 1024                    // fp32 x tile, 32KB
#define OFF_RAW1 (OFF_RAW0 + 32768)
#define OFF_XH   (OFF_RAW1 + 32768)      // 64 x 272
#define OFF_XL   (OFF_XH + BM * RSTRIDE)
#define OFF_ZH   (OFF_XL + BM * RSTRIDE) // 128 x 272
#define OFF_ZL   (OFF_ZH + D * RSTRIDE)
#define SMEM_TOTAL (OFF_ZL + D * RSTRIDE)

__device__ __forceinline__ uint32_t smem_u32(const void* p) {
    uint32_t a;
    asm("{ .reg .u64 t; cvta.to.shared.u64 t, %1; cvt.u32.u64 %0, t; }" : "=r"(a) : "l"(p));
    return a;
}
#define CP_ASYNC16(s, g) \
    asm volatile("cp.async.cg.shared.global [%0], [%1], 16;" :: "r"(s), "l"(g) : "memory")
#define CP_COMMIT() asm volatile("cp.async.commit_group;" ::: "memory")
#define CP_WAIT1()  asm volatile("cp.async.wait_group 1;" ::: "memory")

#define LDMATRIX_X4(r0, r1, r2, r3, a)                                          \
    asm volatile("ldmatrix.sync.aligned.m8n8.x4.shared.b16 {%0,%1,%2,%3}, [%4];" \
                 : "=r"(r0), "=r"(r1), "=r"(r2), "=r"(r3) : "r"(a))

#define MMA16816(d, a0, a1, a2, a3, b0, b1)                                     \
    asm volatile("mma.sync.aligned.m16n8k16.row.col.f32.bf16.bf16.f32 "         \
                 "{%0,%1,%2,%3}, {%4,%5,%6,%7}, {%8,%9}, {%0,%1,%2,%3};"        \
                 : "+f"((d)[0]), "+f"((d)[1]), "+f"((d)[2]), "+f"((d)[3])       \
                 : "r"(a0), "r"(a1), "r"(a2), "r"(a3), "r"(b0), "r"(b1))

__device__ __forceinline__ float asinh_fast(float v) {
    float av = fabsf(v);
    float s  = sqrtf(fmaf(av, av, 1.0f));
    float l  = __logf(av + s);
    return copysignf(l, v);
}

// ---------------------------------------------------------------------------
// Prelude: per-column constants + z^T bf16 hi/lo (compact n-major layout).
// ---------------------------------------------------------------------------
__global__ void hmlr_prelude(const float* __restrict__ z, const float* __restrict__ r) {
    int n = threadIdx.x;   // output column = B row
    float s = 0.0f;
    #pragma unroll 8
    for (int k = 0; k < D; k++) {
        float v = z[k * D + n];
        s = fmaf(v, v, s);
    }
    float zn = fmaxf(sqrtf(s), 1e-15f);
    float t  = 2.0f * r[n];
    g_A[n] = coshf(t) / zn;
    g_B[n] = sinhf(t);
    g_C[n] = 2.0f * zn;

    __nv_bfloat16* zh = (__nv_bfloat16*)g_zh;
    __nv_bfloat16* zl = (__nv_bfloat16*)g_zl;
    #pragma unroll 4
    for (int k = 0; k < D; k++) {
        float v = z[k * D + n];                 // B[n][k] = z[k][n]
        __nv_bfloat16 h = __float2bfloat16_rn(v);
        float res = v - __bfloat162float(h);
        zh[n * D + k] = h;
        zl[n * D + k] = __float2bfloat16_rn(res);
    }
}

// ---------------------------------------------------------------------------
// Persistent fused kernel. Each CTA owns one SM, loops over 64-row tiles.
//   z hi/lo staged to SMEM once. x tiles double-buffered via cp.async.
//   inner = xh*zh^T + xh*zl^T + xl*zh^T via mma.sync bf16 (fp32 accum in regs).
// ---------------------------------------------------------------------------
__global__ __launch_bounds__(NTHR, 1)
void hmlr_mma(const float* __restrict__ x, float* __restrict__ out,
              int nTiles, int step) {
    extern __shared__ unsigned char smem[];
    const uint32_t sb = smem_u32(smem);
    const int tid  = threadIdx.x;
    const int wid  = tid >> 5;
    const int lane = tid & 31;

    const int t0 = blockIdx.x;

    // ---- issue preloads for tiles t0, t0+step ----
    {
        const char* xg0 = (const char*)(x + (size_t)t0 * BM * D);
        #pragma unroll
        for (int j = 0; j < 4; j++) {
            uint32_t off = (uint32_t)(tid + j * NTHR) * 16u;
            CP_ASYNC16(sb + OFF_RAW0 + off, xg0 + off);
        }
        CP_COMMIT();
        if (t0 + step < nTiles) {
            const char* xg1 = (const char*)(x + (size_t)(t0 + step) * BM * D);
            #pragma unroll
            for (int j = 0; j < 4; j++) {
                uint32_t off = (uint32_t)(tid + j * NTHR) * 16u;
                CP_ASYNC16(sb + OFF_RAW1 + off, xg1 + off);
            }
        }
        CP_COMMIT();
    }

    // ---- stage z hi/lo into padded smem (once) ----
    {
        const float4* zh4 = (const float4*)g_zh;
        const float4* zl4 = (const float4*)g_zl;
        #pragma unroll
        for (int i = 0; i < 4; i++) {
            int idx = tid + i * NTHR;            // 2048 float4 per array
            int n = idx >> 4, c = idx & 15;
            uint32_t doff = (uint32_t)(n * RSTRIDE + c * 16);
            *(float4*)(smem + OFF_ZH + doff) = zh4[idx];
            *(float4*)(smem + OFF_ZL + doff) = zl4[idx];
        }
    }

    // ---- per-thread constants / addressing ----
    const int rb = (wid & 3) << 4;               // warp row base   (0..48)
    const int cb = (wid >> 2) << 5;              // warp col base   (0..96)
    const int g  = lane >> 3, rr = lane & 7;

    // A ldmatrix lane address offset (within XH/XL tile)
    const uint32_t offA = (uint32_t)((rb + ((g & 1) << 3) + rr) * RSTRIDE + ((g >> 1) << 4));
    // B ldmatrix lane address offsets for the two n16 sub-tiles
    const uint32_t offB0 = (uint32_t)((cb + 0  + ((g >> 1) << 3) + rr) * RSTRIDE + ((g & 1) << 4));
    const uint32_t offB1 = (uint32_t)((cb + 16 + ((g >> 1) << 3) + rr) * RSTRIDE + ((g & 1) << 4));

    // per-thread output columns: q in 0..3 -> cols cb + q*8 + (lane%4)*2 + {0,1}
    float kA[8], kB[8], kC[8];
    {
        const int cpair = (lane & 3) << 1;
        #pragma unroll
        for (int q = 0; q < 4; q++) {
            int c = cb + q * 8 + cpair;
            kA[2 * q]     = g_A[c];     kB[2 * q]     = g_B[c];     kC[2 * q]     = g_C[c];
            kA[2 * q + 1] = g_A[c + 1]; kB[2 * q + 1] = g_B[c + 1]; kC[2 * q + 1] = g_C[c + 1];
        }
    }

    float* lam = (float*)(smem + OFF_LAM);
    const int rowT0 = rb + (lane >> 2);          // accum row (regs 0,1)
    const int rowT1 = rowT0 + 8;                 // accum row (regs 2,3)

    // ================= main persistent loop =================
    int p = 0;
    for (int t = t0; t < nTiles; t += step, p ^= 1) {
        const uint32_t rawOff = p ? OFF_RAW1 : OFF_RAW0;

        CP_WAIT1();
        __syncthreads();

        // ---- convert raw fp32 tile -> bf16 hi/lo (padded layout) + lambda ----
        {
            const float4* raw4 = (const float4*)(smem + rawOff);
            #pragma unroll
            for (int it = 0; it < 2; it++) {
                int idx = tid + it * NTHR;       // 1024 chunks of 8 floats
                int row = idx >> 4, c = idx & 15;
                float4 v0 = raw4[idx * 2];
                float4 v1 = raw4[idx * 2 + 1];
                float f[8] = {v0.x, v0.y, v0.z, v0.w, v1.x, v1.y, v1.z, v1.w};
                uint32_t hp[4], lp[4];
                #pragma unroll
                for (int j = 0; j < 4; j++) {
                    float a = f[2 * j], b = f[2 * j + 1];
                    __nv_bfloat16 ha = __float2bfloat16_rn(a);
                    __nv_bfloat16 hb = __float2bfloat16_rn(b);
                    float ra = a - __bfloat162float(ha);
                    float rc = b - __bfloat162float(hb);
                    hp[j] = (uint32_t)__bfloat16_as_ushort(ha) |
                            ((uint32_t)__bfloat16_as_ushort(hb) << 16);
                    lp[j] = (uint32_t)__bfloat16_as_ushort(__float2bfloat16_rn(ra)) |
                            ((uint32_t)__bfloat16_as_ushort(__float2bfloat16_rn(rc)) << 16);
                }
                uint32_t doff = (uint32_t)(row * RSTRIDE + c * 16);
                *(uint4*)(smem + OFF_XH + doff) = make_uint4(hp[0], hp[1], hp[2], hp[3]);
                *(uint4*)(smem + OFF_XL + doff) = make_uint4(lp[0], lp[1], lp[2], lp[3]);

                float sq = 0.0f;
                #pragma unroll
                for (int j = 0; j < 8; j++) sq = fmaf(f[j], f[j], sq);
                #pragma unroll
                for (int o = 8; o > 0; o >>= 1)
                    sq += __shfl_xor_sync(0xffffffffu, sq, o);
                if ((lane & 15) == 0) lam[row] = 2.0f / (1.0f - sq);
            }
        }
        __syncthreads();

        // ---- prefetch tile t + 2*step into the raw buffer just freed ----
        if (t + 2 * step < nTiles) {
            const char* xg = (const char*)(x + (size_t)(t + 2 * step) * BM * D);
            #pragma unroll
            for (int j = 0; j < 4; j++) {
                uint32_t off = (uint32_t)(tid + j * NTHR) * 16u;
                CP_ASYNC16(sb + rawOff + off, xg + off);
            }
        }
        CP_COMMIT();

        // ---- MMA: 3-term bf16 split, fp32 accum in regs ----
        float acc[4][4];
        #pragma unroll
        for (int q = 0; q < 4; q++)
            #pragma unroll
            for (int j = 0; j < 4; j++) acc[q][j] = 0.0f;

        const uint32_t aH = sb + OFF_XH + offA, aL = sb + OFF_XL + offA;
        const uint32_t bH0 = sb + OFF_ZH + offB0, bH1 = sb + OFF_ZH + offB1;
        const uint32_t bL0 = sb + OFF_ZL + offB0, bL1 = sb + OFF_ZL + offB1;

        #pragma unroll
        for (int ks = 0; ks < 8; ks++) {
            const uint32_t kd = (uint32_t)ks * 32u;
            uint32_t ah[4], al[4], bh[8], bl[8];
            LDMATRIX_X4(ah[0], ah[1], ah[2], ah[3], aH + kd);
            LDMATRIX_X4(bh[0], bh[1], bh[2], bh[3], bH0 + kd);
            LDMATRIX_X4(bh[4], bh[5], bh[6], bh[7], bH1 + kd);
            MMA16816(acc[0], ah[0], ah[1], ah[2], ah[3], bh[0], bh[1]);
            MMA16816(acc[1], ah[0], ah[1], ah[2], ah[3], bh[2], bh[3]);
            MMA16816(acc[2], ah[0], ah[1], ah[2], ah[3], bh[4], bh[5]);
            MMA16816(acc[3], ah[0], ah[1], ah[2], ah[3], bh[6], bh[7]);
            LDMATRIX_X4(al[0], al[1], al[2], al[3], aL + kd);
            MMA16816(acc[0], al[0], al[1], al[2], al[3], bh[0], bh[1]);
            MMA16816(acc[1], al[0], al[1], al[2], al[3], bh[2], bh[3]);
            MMA16816(acc[2], al[0], al[1], al[2], al[3], bh[4], bh[5]);
            MMA16816(acc[3], al[0], al[1], al[2], al[3], bh[6], bh[7]);
            LDMATRIX_X4(bl[0], bl[1], bl[2], bl[3], bL0 + kd);
            LDMATRIX_X4(bl[4], bl[5], bl[6], bl[7], bL1 + kd);
            MMA16816(acc[0], ah[0], ah[1], ah[2], ah[3], bl[0], bl[1]);
            MMA16816(acc[1], ah[0], ah[1], ah[2], ah[3], bl[2], bl[3]);
            MMA16816(acc[2], ah[0], ah[1], ah[2], ah[3], bl[4], bl[5]);
            MMA16816(acc[3], ah[0], ah[1], ah[2], ah[3], bl[6], bl[7]);
        }

        // ---- epilogue: Poincare MLR arcsinh ----
        {
            const float L0   = lam[rowT0];
            const float L1   = lam[rowT1];
            float* o0 = out + ((size_t)t * BM + rowT0) * D;
            float* o1 = out + ((size_t)t * BM + rowT1) * D;
            const int cpair = (lane & 3) << 1;
            #pragma unroll
            for (int q = 0; q < 4; q++) {
                int c = cb + q * 8 + cpair;
                float2 w0, w1;
                w0.x = kC[2*q]   * asinh_fast(fmaf(L0 * acc[q][0], kA[2*q],   -(L0 - 1.0f) * kB[2*q]));
                w0.y = kC[2*q+1] * asinh_fast(fmaf(L0 * acc[q][1], kA[2*q+1], -(L0 - 1.0f) * kB[2*q+1]));
                w1.x = kC[2*q]   * asinh_fast(fmaf(L1 * acc[q][2], kA[2*q],   -(L1 - 1.0f) * kB[2*q]));
                w1.y = kC[2*q+1] * asinh_fast(fmaf(L1 * acc[q][3], kA[2*q+1], -(L1 - 1.0f) * kB[2*q+1]));
                *(float2*)(o0 + c) = w0;
                *(float2*)(o1 + c) = w1;
            }
        }
        __syncthreads();   // lam / xh / xl reuse safety before next iteration
    }
}

// ---------------------------------------------------------------------------
extern "C" void kernel_launch(void* const* d_in, const int* in_sizes, int n_in,
                              void* d_out, int out_size) {
    const float* x = (const float*)d_in[0];   // [N, 128]
    const float* z = (const float*)d_in[1];   // [128, 128]
    const float* r = (const float*)d_in[2];   // [128]
    float* out = (float*)d_out;

    int nRows  = in_sizes[0] / D;             // 131072
    int nTiles = nRows / BM;                  // 2048

    int sms = 148;
    cudaDeviceGetAttribute(&sms, cudaDevAttrMultiProcessorCount, 0);
    if (sms > nTiles) sms = nTiles;

    cudaFuncSetAttribute(hmlr_mma, cudaFuncAttributeMaxDynamicSharedMemorySize, SMEM_TOTAL);

    hmlr_prelude<<<1, D>>>(z, r);
    hmlr_mma<<<sms, NTHR, SMEM_TOTAL>>>(x, out, nTiles, sms);
}

// round 7
// speedup vs baseline: 2.2475x; 1.3257x over previous
#include <cuda_runtime.h>
#include <cuda_bf16.h>
#include <cstdint>

#define D       128
#define BM      64          // rows per x tile
#define NTHR    512         // 16 warps
#define RSTRIDE 272         // padded smem row stride (17 x 16B) -> conflict-free ldmatrix

// ---------------- smem layout (bytes) ----------------
#define OFF_LAM  0                        // 64 floats
#define OFF_CA   256                      // 128 floats
#define OFF_CB   768
#define OFF_CC   1280
#define OFF_ZSQ  1792                     // 128 floats
#define OFF_RAW  2304                     // fp32 x tile, 32 KB
#define OFF_XH   (OFF_RAW + 32768)        // 64 x 272 bf16 tile
#define OFF_XL   (OFF_XH + BM * RSTRIDE)
#define OFF_ZH   (OFF_XL + BM * RSTRIDE)  // 128 x 272
#define OFF_ZL   (OFF_ZH + D * RSTRIDE)
#define SMEM_TOTAL (OFF_ZL + D * RSTRIDE) // ~136 KB

__device__ __forceinline__ uint32_t smem_u32(const void* p) {
    uint32_t a;
    asm("{ .reg .u64 t; cvta.to.shared.u64 t, %1; cvt.u32.u64 %0, t; }" : "=r"(a) : "l"(p));
    return a;
}
#define CP_ASYNC16(s, g) \
    asm volatile("cp.async.cg.shared.global [%0], [%1], 16;" :: "r"(s), "l"(g) : "memory")
#define CP_COMMIT() asm volatile("cp.async.commit_group;" ::: "memory")
#define CP_WAIT0()  asm volatile("cp.async.wait_group 0;" ::: "memory")

#define LDMATRIX_X4(r0, r1, r2, r3, a)                                           \
    asm volatile("ldmatrix.sync.aligned.m8n8.x4.shared.b16 {%0,%1,%2,%3}, [%4];" \
                 : "=r"(r0), "=r"(r1), "=r"(r2), "=r"(r3) : "r"(a))

#define MMA16816(d, a0, a1, a2, a3, b0, b1)                                      \
    asm volatile("mma.sync.aligned.m16n8k16.row.col.f32.bf16.bf16.f32 "          \
                 "{%0,%1,%2,%3}, {%4,%5,%6,%7}, {%8,%9}, {%0,%1,%2,%3};"         \
                 : "+f"((d)[0]), "+f"((d)[1]), "+f"((d)[2]), "+f"((d)[3])        \
                 : "r"(a0), "r"(a1), "r"(a2), "r"(a3), "r"(b0), "r"(b1))

__device__ __forceinline__ float sqrt_approx(float v) {
    float o;
    asm("sqrt.approx.f32 %0, %1;" : "=f"(o) : "f"(v));
    return o;
}
__device__ __forceinline__ float asinh_fast(float v) {
    float av = fabsf(v);
    float s  = sqrt_approx(fmaf(av, av, 1.0f));
    float l  = __logf(av + s);
    return copysignf(l, v);
}

// ---------------------------------------------------------------------------
// Single persistent fused kernel.
//   startup: stage z -> bf16 hi/lo smem (once per CTA), per-col consts,
//            hoist B fragments (both hi and lo) into registers.
//   loop:    cp.async x tile -> convert to bf16 hi/lo + lambda -> HMMA
//            (A from smem, B from regs) -> arcsinh epilogue.
//   inner = xh*zh^T + xh*zl^T + xl*zh^T  (fp32 accum, rel err ~4e-6)
// ---------------------------------------------------------------------------
__global__ __launch_bounds__(NTHR, 1)
void hmlr_fused(const float* __restrict__ x, const float* __restrict__ z,
                const float* __restrict__ r, float* __restrict__ out,
                int nTiles, int step) {
    extern __shared__ unsigned char smem[];
    const uint32_t sb = smem_u32(smem);
    const int tid  = threadIdx.x;
    const int wid  = tid >> 5;
    const int lane = tid & 31;
    const int t0   = blockIdx.x;

    // ---- kick off first x tile load ASAP ----
    {
        const char* xg = (const char*)(x + (size_t)t0 * BM * D);
        #pragma unroll
        for (int j = 0; j < 4; j++) {
            uint32_t off = (uint32_t)(tid + j * NTHR) * 16u;
            CP_ASYNC16(sb + OFF_RAW + off, xg + off);
        }
        CP_COMMIT();
    }

    // ---- zero column-norm accumulators ----
    if (tid < D) ((float*)(smem + OFF_ZSQ))[tid] = 0.0f;
    __syncthreads();

    // ---- stage z -> bf16 hi/lo [n][k] padded layout; accumulate norms ----
    {
        const int n  = tid & 127;
        const int kq = tid >> 7;                 // 0..3, 32 k each
        float sq = 0.0f;
        #pragma unroll 8
        for (int kk = 0; kk < 32; kk++) {
            int k = kq * 32 + kk;
            float v = z[(size_t)k * D + n];      // coalesced across warp (n contiguous)
            __nv_bfloat16 h = __float2bfloat16_rn(v);
            float res = v - __bfloat162float(h);
            *(__nv_bfloat16*)(smem + OFF_ZH + n * RSTRIDE + k * 2) = h;
            *(__nv_bfloat16*)(smem + OFF_ZL + n * RSTRIDE + k * 2) = __float2bfloat16_rn(res);
            sq = fmaf(v, v, sq);
        }
        atomicAdd((float*)(smem + OFF_ZSQ) + n, sq);
    }
    __syncthreads();

    // ---- per-column constants ----
    if (tid < D) {
        float zn = fmaxf(sqrtf(((const float*)(smem + OFF_ZSQ))[tid]), 1e-15f);
        float t  = 2.0f * r[tid];
        ((float*)(smem + OFF_CA))[tid] = coshf(t) / zn;
        ((float*)(smem + OFF_CB))[tid] = sinhf(t);
        ((float*)(smem + OFF_CC))[tid] = 2.0f * zn;
    }
    __syncthreads();

    // ---- warp tiling: m32 x n16. 2 row bands x 8 col bands ----
    const int rb = (wid & 1) << 5;               // 0 / 32
    const int cb = (wid >> 1) << 4;              // 0..112
    const int g  = lane >> 3, rr = lane & 7;

    // A ldmatrix offsets (m16 x k16 per x4), two m16 tiles
    const uint32_t offA  = (uint32_t)((rb + ((g & 1) << 3) + rr) * RSTRIDE + ((g >> 1) << 4));
    const uint32_t aH0 = sb + OFF_XH + offA;
    const uint32_t aH1 = aH0 + 16 * RSTRIDE;
    const uint32_t aL0 = sb + OFF_XL + offA;
    const uint32_t aL1 = aL0 + 16 * RSTRIDE;

    // B ldmatrix offset (n16 x k16 per x4)
    const uint32_t offB = (uint32_t)((cb + ((g >> 1) << 3) + rr) * RSTRIDE + ((g & 1) << 4));

    // ---- hoist B fragments (hi and lo) into registers: z is constant ----
    uint32_t bh[8][4], bl[8][4];
    {
        const uint32_t bHb = sb + OFF_ZH + offB;
        const uint32_t bLb = sb + OFF_ZL + offB;
        #pragma unroll
        for (int ks = 0; ks < 8; ks++) {
            LDMATRIX_X4(bh[ks][0], bh[ks][1], bh[ks][2], bh[ks][3], bHb + ks * 32u);
            LDMATRIX_X4(bl[ks][0], bl[ks][1], bl[ks][2], bl[ks][3], bLb + ks * 32u);
        }
    }

    // ---- per-thread epilogue constants (4 output cols) ----
    float kA[4], kB[4], kC[4];
    {
        const int c = cb + ((lane & 3) << 1);
        const float* sA = (const float*)(smem + OFF_CA);
        const float* sB = (const float*)(smem + OFF_CB);
        const float* sC = (const float*)(smem + OFF_CC);
        kA[0] = sA[c];     kB[0] = sB[c];     kC[0] = sC[c];
        kA[1] = sA[c + 1]; kB[1] = sB[c + 1]; kC[1] = sC[c + 1];
        kA[2] = sA[c + 8]; kB[2] = sB[c + 8]; kC[2] = sC[c + 8];
        kA[3] = sA[c + 9]; kB[3] = sB[c + 9]; kC[3] = sC[c + 9];
    }

    float* lam = (float*)(smem + OFF_LAM);

    // ================= persistent tile loop =================
    for (int t = t0; t < nTiles; t += step) {
        CP_WAIT0();
        __syncthreads();                          // raw tile ready

        // ---- convert raw fp32 -> bf16 hi/lo + lambda ----
        {
            const int row   = tid >> 3;           // 0..63
            const int chunk = tid & 7;            // 16 floats each
            const float4* rp = (const float4*)(smem + OFF_RAW + row * 512 + chunk * 64);
            float4 v[4];
            v[0] = rp[0]; v[1] = rp[1]; v[2] = rp[2]; v[3] = rp[3];
            float f[16];
            #pragma unroll
            for (int j = 0; j < 4; j++) {
                f[4 * j] = v[j].x; f[4 * j + 1] = v[j].y;
                f[4 * j + 2] = v[j].z; f[4 * j + 3] = v[j].w;
            }
            uint32_t hp[8], lp[8];
            #pragma unroll
            for (int j = 0; j < 8; j++) {
                float a = f[2 * j], b = f[2 * j + 1];
                __nv_bfloat16 ha = __float2bfloat16_rn(a);
                __nv_bfloat16 hb = __float2bfloat16_rn(b);
                float ra = a - __bfloat162float(ha);
                float rc = b - __bfloat162float(hb);
                hp[j] = (uint32_t)__bfloat16_as_ushort(ha) |
                        ((uint32_t)__bfloat16_as_ushort(hb) << 16);
                lp[j] = (uint32_t)__bfloat16_as_ushort(__float2bfloat16_rn(ra)) |
                        ((uint32_t)__bfloat16_as_ushort(__float2bfloat16_rn(rc)) << 16);
            }
            uint32_t doff = (uint32_t)(row * RSTRIDE + chunk * 32);
            *(uint4*)(smem + OFF_XH + doff)      = make_uint4(hp[0], hp[1], hp[2], hp[3]);
            *(uint4*)(smem + OFF_XH + doff + 16) = make_uint4(hp[4], hp[5], hp[6], hp[7]);
            *(uint4*)(smem + OFF_XL + doff)      = make_uint4(lp[0], lp[1], lp[2], lp[3]);
            *(uint4*)(smem + OFF_XL + doff + 16) = make_uint4(lp[4], lp[5], lp[6], lp[7]);

            float sq = 0.0f;
            #pragma unroll
            for (int j = 0; j < 16; j++) sq = fmaf(f[j], f[j], sq);
            sq += __shfl_xor_sync(0xffffffffu, sq, 1);
            sq += __shfl_xor_sync(0xffffffffu, sq, 2);
            sq += __shfl_xor_sync(0xffffffffu, sq, 4);
            if ((lane & 7) == 0) lam[row] = 2.0f / (1.0f - sq);
        }
        __syncthreads();                          // XH/XL + lam ready, raw free

        // ---- prefetch next tile into raw (overlaps MMA + epilogue) ----
        if (t + step < nTiles) {
            const char* xg = (const char*)(x + (size_t)(t + step) * BM * D);
            #pragma unroll
            for (int j = 0; j < 4; j++) {
                uint32_t off = (uint32_t)(tid + j * NTHR) * 16u;
                CP_ASYNC16(sb + OFF_RAW + off, xg + off);
            }
        }
        CP_COMMIT();

        // ---- MMA: A from smem, B from regs; 12 HMMA per ks ----
        float acc[2][2][4];
        #pragma unroll
        for (int mi = 0; mi < 2; mi++)
            #pragma unroll
            for (int ni = 0; ni < 2; ni++)
                #pragma unroll
                for (int j = 0; j < 4; j++) acc[mi][ni][j] = 0.0f;

        #pragma unroll
        for (int ks = 0; ks < 8; ks++) {
            const uint32_t kd = (uint32_t)ks * 32u;
            uint32_t a0[4], a1[4], l0[4], l1[4];
            LDMATRIX_X4(a0[0], a0[1], a0[2], a0[3], aH0 + kd);
            LDMATRIX_X4(a1[0], a1[1], a1[2], a1[3], aH1 + kd);
            // hi * hi
            MMA16816(acc[0][0], a0[0], a0[1], a0[2], a0[3], bh[ks][0], bh[ks][1]);
            MMA16816(acc[0][1], a0[0], a0[1], a0[2], a0[3], bh[ks][2], bh[ks][3]);
            MMA16816(acc[1][0], a1[0], a1[1], a1[2], a1[3], bh[ks][0], bh[ks][1]);
            MMA16816(acc[1][1], a1[0], a1[1], a1[2], a1[3], bh[ks][2], bh[ks][3]);
            LDMATRIX_X4(l0[0], l0[1], l0[2], l0[3], aL0 + kd);
            LDMATRIX_X4(l1[0], l1[1], l1[2], l1[3], aL1 + kd);
            // lo * hi
            MMA16816(acc[0][0], l0[0], l0[1], l0[2], l0[3], bh[ks][0], bh[ks][1]);
            MMA16816(acc[0][1], l0[0], l0[1], l0[2], l0[3], bh[ks][2], bh[ks][3]);
            MMA16816(acc[1][0], l1[0], l1[1], l1[2], l1[3], bh[ks][0], bh[ks][1]);
            MMA16816(acc[1][1], l1[0], l1[1], l1[2], l1[3], bh[ks][2], bh[ks][3]);
            // hi * lo
            MMA16816(acc[0][0], a0[0], a0[1], a0[2], a0[3], bl[ks][0], bl[ks][1]);
            MMA16816(acc[0][1], a0[0], a0[1], a0[2], a0[3], bl[ks][2], bl[ks][3]);
            MMA16816(acc[1][0], a1[0], a1[1], a1[2], a1[3], bl[ks][0], bl[ks][1]);
            MMA16816(acc[1][1], a1[0], a1[1], a1[2], a1[3], bl[ks][2], bl[ks][3]);
        }

        // ---- epilogue: Poincare MLR arcsinh, fp32 out ----
        {
            const int cB = cb + ((lane & 3) << 1);
            #pragma unroll
            for (int mi = 0; mi < 2; mi++) {
                const int rowA = rb + mi * 16 + (lane >> 2);
                const float L0 = lam[rowA];
                const float L1 = lam[rowA + 8];
                const float M0 = -(L0 - 1.0f), M1 = -(L1 - 1.0f);
                float* o0 = out + ((size_t)t * BM + rowA) * D;
                float* o1 = o0 + 8 * D;
                #pragma unroll
                for (int ni = 0; ni < 2; ni++) {
                    const float* a = acc[mi][ni];
                    const int c  = cB + ni * 8;
                    const int k0 = ni * 2, k1 = ni * 2 + 1;
                    float2 w0, w1;
                    w0.x = kC[k0] * asinh_fast(fmaf(L0 * a[0], kA[k0], M0 * kB[k0]));
                    w0.y = kC[k1] * asinh_fast(fmaf(L0 * a[1], kA[k1], M0 * kB[k1]));
                    w1.x = kC[k0] * asinh_fast(fmaf(L1 * a[2], kA[k0], M1 * kB[k0]));
                    w1.y = kC[k1] * asinh_fast(fmaf(L1 * a[3], kA[k1], M1 * kB[k1]));
                    *(float2*)(o0 + c) = w0;
                    *(float2*)(o1 + c) = w1;
                }
            }
        }
        __syncthreads();   // protect XH/XL + lam before next convert
    }
}

// ---------------------------------------------------------------------------
extern "C" void kernel_launch(void* const* d_in, const int* in_sizes, int n_in,
                              void* d_out, int out_size) {
    const float* x = (const float*)d_in[0];   // [N, 128]
    const float* z = (const float*)d_in[1];   // [128, 128]
    const float* r = (const float*)d_in[2];   // [128]
    float* out = (float*)d_out;

    int nRows  = in_sizes[0] / D;             // 131072
    int nTiles = nRows / BM;                  // 2048

    int sms = 148;
    cudaDeviceGetAttribute(&sms, cudaDevAttrMultiProcessorCount, 0);
    if (sms > nTiles) sms = nTiles;

    cudaFuncSetAttribute(hmlr_fused, cudaFuncAttributeMaxDynamicSharedMemorySize, SMEM_TOTAL);
    hmlr_fused<<<sms, NTHR, SMEM_TOTAL>>>(x, z, r, out, nTiles, sms);
}